// round 4
// baseline (speedup 1.0000x reference)
#include <cuda_runtime.h>
#include <cuda_bf16.h>

// Problem constants
#define B_   8
#define LQ_  512
#define LK_  512
#define D_   512
#define H_   128
#define M_   (B_ * LQ_)   // 4096 rows per projection

// Scratch for projected Q and K (no cudaMalloc allowed)
__device__ float g_Q[M_ * H_];
__device__ float g_K[M_ * H_];

__device__ __forceinline__ float fast_tanh(float x) {
    float y;
    asm("tanh.approx.f32 %0, %1;" : "=f"(y) : "f"(x));
    return y;
}

// Packed fp32x2 FMA (Blackwell FFMA2) — IEEE fp32 fused, bit-identical to fmaf.
__device__ __forceinline__ unsigned long long fma_f32x2(
    unsigned long long a, unsigned long long b, unsigned long long c) {
    unsigned long long d;
    asm("fma.rn.f32x2 %0, %1, %2, %3;" : "=l"(d) : "l"(a), "l"(b), "l"(c));
    return d;
}
__device__ __forceinline__ unsigned long long pack2(float lo, float hi) {
    unsigned long long p;
    asm("mov.b64 %0, {%1, %2};" : "=l"(p) : "f"(lo), "f"(hi));
    return p;
}
__device__ __forceinline__ void unpack2(unsigned long long p, float& lo, float& hi) {
    asm("mov.b64 {%0, %1}, %2;" : "=f"(lo), "=f"(hi) : "l"(p));
}

// ---------------------------------------------------------------------------
// Projection GEMM: Y[m, h] = sum_d X[m, d] * W[d, h]
// M=4096 (x2 matrices), K=512, N=128.  BM=32, BN=128, BK=32. 256 threads.
// 256 blocks -> all 148 SMs busy, ~2 blocks/SM concurrent (16 warps/SM).
// Thread tile: 4 rows (2 packed f32x2 pairs) x 4 cols -> 8 FFMA2 per kk.
// As transposed [BK][BM+8]: row-pairs read as one broadcast LDS.128.
// ---------------------------------------------------------------------------
#define BM 32
#define BK 32
#define BN 128
#define APAD 8   // As row stride 40 floats = 160B (16B-aligned rows)

__global__ __launch_bounds__(256) void proj_kernel(
    const float* __restrict__ qs, const float* __restrict__ ks,
    const float* __restrict__ Wq, const float* __restrict__ Wk)
{
    const int nb = M_ / BM;                 // 128 blocks per projection
    bool isK = (blockIdx.x >= nb);
    int bm = isK ? (blockIdx.x - nb) : blockIdx.x;
    const float* __restrict__ X = isK ? ks : qs;
    const float* __restrict__ W = isK ? Wk : Wq;
    float* __restrict__ Y = isK ? g_K : g_Q;

    __shared__ float As[BK][BM + APAD];  // transposed: As[k][m]
    __shared__ float Bs[BK][BN];

    int tid = threadIdx.x;
    int tx = tid & 31;       // col group (4 cols)
    int ty = tid >> 5;       // row group (4 rows each, 8 groups)

    // A-tile load: 32 rows x 32 k = 1024 floats = 256 float4, one per thread
    int ar  = tid >> 3;      // row 0..31
    int ac4 = tid & 7;       // k-col group 0..7
    // B-tile load: 32 x 128 = 4096 floats = 1024 float4, four per thread
    int br  = tid >> 5;      // rows br + 8*i
    int bc4 = tid & 31;

    const float* Xp  = X + (size_t)(bm * BM + ar) * D_ + ac4 * 4;
    const float* Wp  = W + (size_t)br * BN + bc4 * 4;

    unsigned long long acc2[2][4];
#pragma unroll
    for (int i = 0; i < 2; i++)
#pragma unroll
        for (int j = 0; j < 4; j++) acc2[i][j] = 0ull;

    // Prefetch first tiles into registers
    float4 pa = *(const float4*)(Xp);
    float4 pb[4];
#pragma unroll
    for (int i = 0; i < 4; i++)
        pb[i] = *(const float4*)(Wp + (size_t)(8 * i) * BN);

    for (int k0 = 0; k0 < D_; k0 += BK) {
        // Stage prefetched tiles into shared
        As[ac4 * 4 + 0][ar] = pa.x;
        As[ac4 * 4 + 1][ar] = pa.y;
        As[ac4 * 4 + 2][ar] = pa.z;
        As[ac4 * 4 + 3][ar] = pa.w;
#pragma unroll
        for (int i = 0; i < 4; i++)
            *(float4*)(&Bs[br + 8 * i][bc4 * 4]) = pb[i];
        __syncthreads();

        // Prefetch next tiles (hidden under compute)
        if (k0 + BK < D_) {
            pa = *(const float4*)(Xp + k0 + BK);
#pragma unroll
            for (int i = 0; i < 4; i++)
                pb[i] = *(const float4*)(Wp + (size_t)(k0 + BK + 8 * i) * BN);
        }

#pragma unroll
        for (int kk = 0; kk < BK; ++kk) {
            // 2 packed row-pairs via one broadcast LDS.128
            ulonglong2 a01 = *(const ulonglong2*)(&As[kk][ty * 4]);
            unsigned long long ap[2] = {a01.x, a01.y};
            float4 bv = *(const float4*)(&Bs[kk][tx * 4]);
            unsigned long long bd[4] = {
                pack2(bv.x, bv.x), pack2(bv.y, bv.y),
                pack2(bv.z, bv.z), pack2(bv.w, bv.w)};
#pragma unroll
            for (int i = 0; i < 2; i++)
#pragma unroll
                for (int j = 0; j < 4; j++)
                    acc2[i][j] = fma_f32x2(ap[i], bd[j], acc2[i][j]);
        }
        __syncthreads();
    }

    // Epilogue: acc2[i][j] = rows (ty*4+2i, +1), col tx*4+j
#pragma unroll
    for (int i = 0; i < 2; i++) {
        float lo[4], hi[4];
#pragma unroll
        for (int j = 0; j < 4; j++) unpack2(acc2[i][j], lo[j], hi[j]);
        size_t r0 = (size_t)(bm * BM + ty * 4 + 2 * i) * H_ + tx * 4;
        *(float4*)(Y + r0)      = make_float4(lo[0], lo[1], lo[2], lo[3]);
        *(float4*)(Y + r0 + H_) = make_float4(hi[0], hi[1], hi[2], hi[3]);
    }
}

// ---------------------------------------------------------------------------
// Score kernel: out[b,q,k] = sum_h wv[h] * tanh(Q[b,q,h] + K[b,k,h])
// 32q x 64k tiles, 256 threads, thread tile 2x4. 1024 blocks.
// MUFU-bound at ~92% of roofline — unchanged.
// ---------------------------------------------------------------------------
#define TQ 32
#define TK 64

__global__ __launch_bounds__(256) void score_kernel(
    const float* __restrict__ wv, float* __restrict__ out)
{
    __shared__ float sq[TQ][65];
    __shared__ float sk[TK][65];
    __shared__ float swv[H_];

    int b  = blockIdx.z;
    int q0 = blockIdx.y * TQ;
    int k0 = blockIdx.x * TK;

    const float* Qb = g_Q + (size_t)(b * LQ_ + q0) * H_;
    const float* Kb = g_K + (size_t)(b * LK_ + k0) * H_;

    int tid = threadIdx.x;
    if (tid < H_) swv[tid] = wv[tid];

    int tx = tid & 15;
    int ty = tid >> 4;

    float acc[2][4];
#pragma unroll
    for (int i = 0; i < 2; i++)
#pragma unroll
        for (int j = 0; j < 4; j++) acc[i][j] = 0.f;

#pragma unroll
    for (int half = 0; half < 2; ++half) {
        __syncthreads();
        for (int i = tid; i < 512; i += 256) {
            int r = i >> 4, c4 = i & 15;
            float4 v = *(const float4*)(Qb + r * H_ + half * 64 + c4 * 4);
            float* dq = &sq[r][c4 * 4];
            dq[0] = v.x; dq[1] = v.y; dq[2] = v.z; dq[3] = v.w;
        }
        for (int i = tid; i < 1024; i += 256) {
            int r = i >> 4, c4 = i & 15;
            float4 w = *(const float4*)(Kb + r * H_ + half * 64 + c4 * 4);
            float* dk = &sk[r][c4 * 4];
            dk[0] = w.x; dk[1] = w.y; dk[2] = w.z; dk[3] = w.w;
        }
        __syncthreads();

#pragma unroll 4
        for (int h = 0; h < 64; ++h) {
            float wvh = swv[half * 64 + h];
            float qv[2], kv[4];
#pragma unroll
            for (int i = 0; i < 2; i++) qv[i] = sq[ty + 16 * i][h];
#pragma unroll
            for (int j = 0; j < 4; j++) kv[j] = sk[tx + 16 * j][h];
#pragma unroll
            for (int i = 0; i < 2; i++)
#pragma unroll
                for (int j = 0; j < 4; j++)
                    acc[i][j] = fmaf(wvh, fast_tanh(qv[i] + kv[j]), acc[i][j]);
        }
    }

    float* ob = out + ((size_t)b * LQ_ + q0) * LK_ + k0;
#pragma unroll
    for (int i = 0; i < 2; i++)
#pragma unroll
        for (int j = 0; j < 4; j++)
            ob[(size_t)(ty + 16 * i) * LK_ + tx + 16 * j] = acc[i][j];
}

// ---------------------------------------------------------------------------

extern "C" void kernel_launch(void* const* d_in, const int* in_sizes, int n_in,
                              void* d_out, int out_size)
{
    const float* qs = (const float*)d_in[0];   // [8,512,512]
    const float* ks = (const float*)d_in[1];   // [8,512,512]
    const float* Wq = (const float*)d_in[2];   // [512,128]
    const float* Wk = (const float*)d_in[3];   // [512,128]
    const float* wv = (const float*)d_in[4];   // [128]
    float* out = (float*)d_out;                // [8,512,512]

    proj_kernel<<<2 * (M_ / BM), 256>>>(qs, ks, Wq, Wk);

    dim3 grid(LK_ / TK, LQ_ / TQ, B_);
    score_kernel<<<grid, 256>>>(wv, out);
}

// round 5
// speedup vs baseline: 1.0762x; 1.0762x over previous
#include <cuda_runtime.h>
#include <cuda_bf16.h>

// Problem constants
#define B_   8
#define LQ_  512
#define LK_  512
#define D_   512
#define H_   128
#define M_   (B_ * LQ_)

// Scratch + sync state (no cudaMalloc allowed)
__device__ float g_Q[M_ * H_];
__device__ float g_K[M_ * H_];
__device__ int   g_done[B_];   // per-batch proj-tile completion counters (target 16)

__device__ __forceinline__ float fast_tanh(float x) {
    float y;
    asm("tanh.approx.f32 %0, %1;" : "=f"(y) : "f"(x));
    return y;
}
__device__ __forceinline__ unsigned long long fma_f32x2(
    unsigned long long a, unsigned long long b, unsigned long long c) {
    unsigned long long d;
    asm("fma.rn.f32x2 %0, %1, %2, %3;" : "=l"(d) : "l"(a), "l"(b), "l"(c));
    return d;
}
__device__ __forceinline__ unsigned long long pack2(float lo, float hi) {
    unsigned long long p;
    asm("mov.b64 %0, {%1, %2};" : "=l"(p) : "f"(lo), "f"(hi));
    return p;
}
__device__ __forceinline__ void unpack2(unsigned long long p, float& lo, float& hi) {
    asm("mov.b64 {%0, %1}, %2;" : "=f"(lo), "=f"(hi) : "l"(p));
}

// ---------------------------------------------------------------------------
// Fused persistent kernel.
//   bids [0, 128):    proj tiles.  Tile = 64 rows of one projection.
//                     Ordering batch-major: bid -> b = bid/16, so batch 0's
//                     16 tiles (8 Q + 8 K) complete first -> early unblock.
//   bids [128, 1152): score tiles (32q x 64k), spin on g_done[b] == 16.
// Proj bids all fit in scheduling wave 1 (148 SMs >= 128 at occ >= 1), so
// score spinners can never deadlock the producers.
// ---------------------------------------------------------------------------
#define PROJ_BIDS 128
#define BK 16
#define TQ 32
#define TK 64

union SmemU {
    struct { float As[BK][72]; float Bs[BK][H_]; } p;        // 12.8 KB
    struct { float sq[TQ][65]; float sk[TK][65]; float swv[H_]; } s; // 25.5 KB
};

__global__ void init_kernel() {
    if (threadIdx.x < B_) g_done[threadIdx.x] = 0;
}

__global__ __launch_bounds__(256) void fused_kernel(
    const float* __restrict__ qs, const float* __restrict__ ks,
    const float* __restrict__ Wq, const float* __restrict__ Wk,
    const float* __restrict__ wv, float* __restrict__ out)
{
    __shared__ SmemU u;
    int bid = blockIdx.x;
    int tid = threadIdx.x;

    if (bid < PROJ_BIDS) {
        // ----------------- projection tile (BM=64, BK=16, BN=128) ---------
        int b   = bid >> 4;          // batch
        int r   = bid & 15;
        int mat = r >> 3;            // 0 = Q, 1 = K
        int t   = r & 7;             // tile within batch (64 rows)
        const float* __restrict__ X = mat ? ks : qs;
        const float* __restrict__ W = mat ? Wk : Wq;
        float* __restrict__ Y       = mat ? g_K : g_Q;
        int row0 = b * LQ_ + t * 64;

        int tx = tid & 31;           // col group (4 cols)
        int ty = tid >> 5;           // row group (8 rows)
        int ar  = tid >> 2, ac4 = tid & 3;     // A load: 64x16 = 256 float4
        int br  = tid >> 5, bc4 = tid & 31;    // B load: 16x128 = 512 float4 (2/thr)

        const float* Xp  = X + (size_t)(row0 + ar) * D_ + ac4 * 4;
        const float* Wp0 = W + (size_t)br * H_ + bc4 * 4;
        const float* Wp1 = W + (size_t)(br + 8) * H_ + bc4 * 4;

        unsigned long long acc2[4][4];
#pragma unroll
        for (int i = 0; i < 4; i++)
#pragma unroll
            for (int j = 0; j < 4; j++) acc2[i][j] = 0ull;

        float4 pa  = *(const float4*)(Xp);
        float4 pb0 = *(const float4*)(Wp0);
        float4 pb1 = *(const float4*)(Wp1);

        for (int k0 = 0; k0 < D_; k0 += BK) {
            u.p.As[ac4 * 4 + 0][ar] = pa.x;
            u.p.As[ac4 * 4 + 1][ar] = pa.y;
            u.p.As[ac4 * 4 + 2][ar] = pa.z;
            u.p.As[ac4 * 4 + 3][ar] = pa.w;
            *(float4*)(&u.p.Bs[br][bc4 * 4])     = pb0;
            *(float4*)(&u.p.Bs[br + 8][bc4 * 4]) = pb1;
            __syncthreads();

            if (k0 + BK < D_) {
                pa  = *(const float4*)(Xp + k0 + BK);
                pb0 = *(const float4*)(Wp0 + (size_t)(k0 + BK) * H_);
                pb1 = *(const float4*)(Wp1 + (size_t)(k0 + BK) * H_);
            }

#pragma unroll
            for (int kk = 0; kk < BK; ++kk) {
                ulonglong2 a01 = *(const ulonglong2*)(&u.p.As[kk][ty * 8]);
                ulonglong2 a23 = *(const ulonglong2*)(&u.p.As[kk][ty * 8 + 4]);
                unsigned long long ap[4] = {a01.x, a01.y, a23.x, a23.y};
                float4 bv = *(const float4*)(&u.p.Bs[kk][tx * 4]);
                unsigned long long bd[4] = {
                    pack2(bv.x, bv.x), pack2(bv.y, bv.y),
                    pack2(bv.z, bv.z), pack2(bv.w, bv.w)};
#pragma unroll
                for (int i = 0; i < 4; i++)
#pragma unroll
                    for (int j = 0; j < 4; j++)
                        acc2[i][j] = fma_f32x2(ap[i], bd[j], acc2[i][j]);
            }
            __syncthreads();
        }

#pragma unroll
        for (int i = 0; i < 4; i++) {
            float lo[4], hi[4];
#pragma unroll
            for (int j = 0; j < 4; j++) unpack2(acc2[i][j], lo[j], hi[j]);
            size_t r0 = (size_t)(row0 + ty * 8 + 2 * i) * H_ + tx * 4;
            *(float4*)(Y + r0)      = make_float4(lo[0], lo[1], lo[2], lo[3]);
            *(float4*)(Y + r0 + H_) = make_float4(hi[0], hi[1], hi[2], hi[3]);
        }

        // Publish: make tile stores visible, then bump the batch counter.
        __syncthreads();
        __threadfence();
        if (tid == 0) atomicAdd(&g_done[b], 1);

    } else {
        // ----------------- score tile (32q x 64k) -------------------------
        int s  = bid - PROJ_BIDS;
        int b  = s >> 7;
        int w  = s & 127;
        int q0 = (w >> 3) * TQ;      // 16 q-tiles
        int k0 = (w & 7) * TK;       // 8 k-tiles

        // Wait for this batch's 16 proj tiles.
        if (tid == 0) {
            while (*(volatile int*)&g_done[b] < 16) __nanosleep(200);
        }
        __syncthreads();
        __threadfence();

        const float* Qb = g_Q + (size_t)(b * LQ_ + q0) * H_;
        const float* Kb = g_K + (size_t)(b * LK_ + k0) * H_;

        if (tid < H_) u.s.swv[tid] = wv[tid];

        int tx = tid & 15;
        int ty = tid >> 4;

        float acc[2][4];
#pragma unroll
        for (int i = 0; i < 2; i++)
#pragma unroll
            for (int j = 0; j < 4; j++) acc[i][j] = 0.f;

#pragma unroll
        for (int half = 0; half < 2; ++half) {
            __syncthreads();
            for (int i = tid; i < 512; i += 256) {
                int r = i >> 4, c4 = i & 15;
                float4 v = *(const float4*)(Qb + r * H_ + half * 64 + c4 * 4);
                float* dq = &u.s.sq[r][c4 * 4];
                dq[0] = v.x; dq[1] = v.y; dq[2] = v.z; dq[3] = v.w;
            }
            for (int i = tid; i < 1024; i += 256) {
                int r = i >> 4, c4 = i & 15;
                float4 wv4 = *(const float4*)(Kb + r * H_ + half * 64 + c4 * 4);
                float* dk = &u.s.sk[r][c4 * 4];
                dk[0] = wv4.x; dk[1] = wv4.y; dk[2] = wv4.z; dk[3] = wv4.w;
            }
            __syncthreads();

#pragma unroll 4
            for (int h = 0; h < 64; ++h) {
                float wvh = u.s.swv[half * 64 + h];
                float qv[2], kv[4];
#pragma unroll
                for (int i = 0; i < 2; i++) qv[i] = u.s.sq[ty + 16 * i][h];
#pragma unroll
                for (int j = 0; j < 4; j++) kv[j] = u.s.sk[tx + 16 * j][h];
#pragma unroll
                for (int i = 0; i < 2; i++)
#pragma unroll
                    for (int j = 0; j < 4; j++)
                        acc[i][j] = fmaf(wvh, fast_tanh(qv[i] + kv[j]), acc[i][j]);
            }
        }

        float* ob = out + ((size_t)b * LQ_ + q0) * LK_ + k0;
#pragma unroll
        for (int i = 0; i < 2; i++)
#pragma unroll
            for (int j = 0; j < 4; j++)
                ob[(size_t)(ty + 16 * i) * LK_ + tx + 16 * j] = acc[i][j];
    }
}

// ---------------------------------------------------------------------------

extern "C" void kernel_launch(void* const* d_in, const int* in_sizes, int n_in,
                              void* d_out, int out_size)
{
    const float* qs = (const float*)d_in[0];   // [8,512,512]
    const float* ks = (const float*)d_in[1];   // [8,512,512]
    const float* Wq = (const float*)d_in[2];   // [512,128]
    const float* Wk = (const float*)d_in[3];   // [512,128]
    const float* wv = (const float*)d_in[4];   // [128]
    float* out = (float*)d_out;                // [8,512,512]

    init_kernel<<<1, 32>>>();
    fused_kernel<<<PROJ_BIDS + B_ * (LQ_ / TQ) * (LK_ / TK), 256>>>(
        qs, ks, Wq, Wk, wv, out);
}